// round 6
// baseline (speedup 1.0000x reference)
#include <cuda_runtime.h>

#define NB    128
#define CIN   8
#define HIN   128
#define WIN   128
#define COUT  64
#define HO    126
#define WO    126
#define PHN   31
#define PWN   31
#define NG    16
#define CPG   4

typedef unsigned long long u64;

__device__ float  g_sext[(size_t)NB * COUT * PHN * PWN];   // max of sign-adjusted conv over window
__device__ float2 g_partial[32 * NB * NG];
__device__ float2 g_stats[NB * NG];

// ---- packed f32x2 helpers (sm_100+) ----
__device__ __forceinline__ u64 pk2(float lo, float hi) {
    u64 r; asm("mov.b64 %0, {%1, %2};" : "=l"(r) : "f"(lo), "f"(hi)); return r;
}
__device__ __forceinline__ void upk2(float& lo, float& hi, u64 p) {
    asm("mov.b64 {%0, %1}, %2;" : "=f"(lo), "=f"(hi) : "l"(p));
}
__device__ __forceinline__ void ffma2(u64& d, u64 a, u64 b) {
    asm("fma.rn.f32x2 %0, %1, %2, %0;" : "+l"(d) : "l"(a), "l"(b));
}
__device__ __forceinline__ void fadd2(u64& d, u64 a) {
    asm("add.rn.f32x2 %0, %1, %0;" : "+l"(d) : "l"(a));
}

// ---------------------------------------------------------------------------
// Pass 1: conv + bias; per-window sign-adjusted max; per-(b,g) partial stats.
// Grid: (32 row-groups, 128 batches, 2 channel-halves), block = 256.
// Thread t: wx = t&31 (4-col window), cb = t>>5 -> channels z*32+cb*4..+3.
// Warp (fixed cb) owns exactly GroupNorm group g = z*8+cb.
// Inner math in packed f32x2; cin loop NOT unrolled (small live set, no spill).
// ---------------------------------------------------------------------------
__global__ __launch_bounds__(256, 2) void conv_pass1(const float* __restrict__ x,
                                                     const float* __restrict__ w,
                                                     const float* __restrict__ bias,
                                                     const float* __restrict__ gnw,
                                                     const float* __restrict__ scale)
{
    const int pr = blockIdx.x;          // 0..31
    const int b  = blockIdx.y;
    const int z  = blockIdx.z;          // channel half
    const int t  = threadIdx.x;

    __shared__ float  xs[CIN][6][132];  // 6 input rows, 128 cols + 4 zero pad
    __shared__ float2 wsm[72][32];      // [cin*9+ky*3+kx][cl] duplicated (w,w)
    __shared__ float2 bsm[32];          // duplicated (b,b)
    __shared__ float  sgsm[32];         // +1 / -1 per channel

    // weights for this half: global layout [co][cin][ky][kx]
    for (int i = t; i < 72 * 32; i += 256) {
        int cl = i & 31, k = i >> 5;
        float v = w[(z * 32 + cl) * 72 + k];
        wsm[k][cl] = make_float2(v, v);
    }
    if (t < 32) {
        float bb = bias[z * 32 + t];
        bsm[t]  = make_float2(bb, bb);
        sgsm[t] = (gnw[z * 32 + t] * scale[z * 32 + t] < 0.f) ? -1.f : 1.f;
    }

    const int h0 = pr * 4;
    for (int i = t; i < CIN * 6 * 32; i += 256) {
        int c4  = i & 31;
        int rr  = (i >> 5) % 6;
        int cin = i / (6 * 32);
        int h   = h0 + rr;
        float4 v = make_float4(0.f, 0.f, 0.f, 0.f);
        if (h < HIN)
            v = *(const float4*)&x[(((size_t)b * CIN + cin) * HIN + h) * WIN + c4 * 4];
        *(float4*)&xs[cin][rr][c4 * 4] = v;
    }
    if (t < CIN * 6) {
        int rr = t % 6, cin = t / 6;
        *(float4*)&xs[cin][rr][128] = make_float4(0.f, 0.f, 0.f, 0.f);
    }
    __syncthreads();

    const int wx   = t & 31;
    const int cb   = t >> 5;
    const int col0 = wx * 4;
    const int R    = (pr == 31) ? 2 : 4;

    float wext[4], sg[4];
#pragma unroll
    for (int j = 0; j < 4; j++) {
        sg[j]   = sgsm[cb * 4 + j];
        wext[j] = -1e30f;
    }
    u64 s2 = 0ULL, q2 = 0ULL;           // packed partial stats

#pragma unroll 1
    for (int r = 0; r < R; r++) {
        u64 accA[4], accB[4];           // cols (0,1) and (2,3) per channel
#pragma unroll
        for (int j = 0; j < 4; j++) { accA[j] = 0ULL; accB[j] = 0ULL; }

#pragma unroll 1
        for (int cin = 0; cin < CIN; cin++) {
#pragma unroll
            for (int ky = 0; ky < 3; ky++) {
                const float* xr = &xs[cin][r + ky][col0];
                float4 xa = *(const float4*)xr;
                float2 xb = *(const float2*)(xr + 4);
                u64 p01 = pk2(xa.x, xa.y);
                u64 p23 = pk2(xa.z, xa.w);
                u64 p45 = pk2(xb.x, xb.y);
                u64 p12 = pk2(xa.y, xa.z);
                u64 p34 = pk2(xa.w, xb.x);
                const u64* w0 = (const u64*)&wsm[cin * 9 + ky * 3 + 0][cb * 4];
                const u64* w1 = (const u64*)&wsm[cin * 9 + ky * 3 + 1][cb * 4];
                const u64* w2 = (const u64*)&wsm[cin * 9 + ky * 3 + 2][cb * 4];
#pragma unroll
                for (int j = 0; j < 4; j++) {
                    u64 W0 = w0[j], W1 = w1[j], W2 = w2[j];
                    ffma2(accA[j], W0, p01);
                    ffma2(accA[j], W1, p12);
                    ffma2(accA[j], W2, p23);
                    ffma2(accB[j], W0, p23);
                    ffma2(accB[j], W1, p34);
                    ffma2(accB[j], W2, p45);
                }
            }
        }

        // epilogue: bias, stats, sign-adjusted window max
#pragma unroll
        for (int j = 0; j < 4; j++) {
            u64 bp = *(const u64*)&bsm[cb * 4 + j];
            u64 a01 = accA[j]; fadd2(a01, bp);
            u64 a23 = accB[j]; fadd2(a23, bp);
            if (wx < 31) {
                fadd2(s2, a01); fadd2(s2, a23);
                ffma2(q2, a01, a01); ffma2(q2, a23, a23);
                float v0, v1, v2, v3;
                upk2(v0, v1, a01); upk2(v2, v3, a23);
                float g0 = sg[j] * v0, g1 = sg[j] * v1;
                float g2 = sg[j] * v2, g3 = sg[j] * v3;
                wext[j] = fmaxf(wext[j], fmaxf(fmaxf(g0, g1), fmaxf(g2, g3)));
            } else {
                fadd2(s2, a01);             // cols 124,125 valid for stats only
                ffma2(q2, a01, a01);
            }
        }
    }

    // pooled window sign-adjusted max
    if (pr < 31 && wx < 31) {
#pragma unroll
        for (int j = 0; j < 4; j++) {
            int co = z * 32 + cb * 4 + j;
            size_t o = (((size_t)b * COUT + co) * PHN + pr) * PWN + wx;
            g_sext[o] = wext[j];
        }
    }

    // warp-level stats reduction; warp cb exclusively owns group z*8+cb
    float sl, sh, ql, qh;
    upk2(sl, sh, s2); upk2(ql, qh, q2);
    float s = sl + sh, q = ql + qh;
#pragma unroll
    for (int o = 16; o > 0; o >>= 1) {
        s += __shfl_down_sync(0xffffffffu, s, o);
        q += __shfl_down_sync(0xffffffffu, q, o);
    }
    if (wx == 0)
        g_partial[(pr * NB + b) * NG + z * 8 + cb] = make_float2(s, q);
}

// ---------------------------------------------------------------------------
// Pass 2: fold 32 row-group partials into mean/rstd per (b, g).
// ---------------------------------------------------------------------------
__global__ void stats_pass2()
{
    int idx = blockIdx.x * 256 + threadIdx.x;   // b*16+g
    if (idx >= NB * NG) return;
    float s = 0.f, q = 0.f;
    for (int pr = 0; pr < 32; pr++) {
        float2 p = g_partial[pr * (NB * NG) + idx];
        s += p.x; q += p.y;
    }
    const float inv = 1.f / (float)(CPG * HO * WO);
    float mean = s * inv;
    float var  = q * inv - mean * mean;
    g_stats[idx] = make_float2(mean, rsqrtf(var + 1e-5f));
}

// ---------------------------------------------------------------------------
// Pass 3: v = |A| * ext + B, clamp.  (ext = max of sign(A)-adjusted conv)
// ---------------------------------------------------------------------------
__global__ void apply_pass3(const float* __restrict__ gnw,
                            const float* __restrict__ gnb,
                            const float* __restrict__ scale,
                            float* __restrict__ out, int n)
{
    int idx = blockIdx.x * 256 + threadIdx.x;
    if (idx >= n) return;
    int tmp = idx / PWN;
    tmp /= PHN;
    int c = tmp % COUT;
    int b = tmp / COUT;

    float2 st = g_stats[b * NG + (c >> 2)];
    float gw = gnw[c], sc = scale[c];
    float A  = st.y * gw * sc;
    float Bt = (gnb[c] - st.x * st.y * gw) * sc;

    float v = fmaf(fabsf(A), g_sext[idx], Bt);
    out[idx] = fminf(fmaxf(v, 0.f), 1.f);
}

// ---------------------------------------------------------------------------
extern "C" void kernel_launch(void* const* d_in, const int* in_sizes, int n_in,
                              void* d_out, int out_size)
{
    const float* x     = (const float*)d_in[0];
    const float* w     = (const float*)d_in[1];
    const float* bias  = (const float*)d_in[2];
    const float* gnw   = (const float*)d_in[3];
    const float* gnb   = (const float*)d_in[4];
    const float* scale = (const float*)d_in[5];
    float* out = (float*)d_out;

    dim3 g1(32, NB, 2);
    conv_pass1<<<g1, 256>>>(x, w, bias, gnw, scale);
    stats_pass2<<<(NB * NG + 255) / 256, 256>>>();
    int n = NB * COUT * PHN * PWN;
    apply_pass3<<<(n + 255) / 256, 256>>>(gnw, gnb, scale, out, n);
}

// round 7
// speedup vs baseline: 1.2700x; 1.2700x over previous
#include <cuda_runtime.h>

#define NB    128
#define CIN   8
#define HIN   128
#define WIN   128
#define COUT  64
#define HO    126
#define WO    126
#define PHN   31
#define PWN   31
#define NG    16
#define CPG   4

typedef unsigned long long u64;

__device__ float  g_sext[(size_t)NB * COUT * PHN * PWN];   // max of sign-adjusted conv over window
__device__ float2 g_partial[32 * NB * NG];
__device__ float2 g_stats[NB * NG];

// ---- packed f32x2 helpers (sm_100+) ----
__device__ __forceinline__ u64 pk2(float lo, float hi) {
    u64 r; asm("mov.b64 %0, {%1, %2};" : "=l"(r) : "f"(lo), "f"(hi)); return r;
}
__device__ __forceinline__ void upk2(float& lo, float& hi, u64 p) {
    asm("mov.b64 {%0, %1}, %2;" : "=f"(lo), "=f"(hi) : "l"(p));
}
__device__ __forceinline__ void ffma2(u64& d, u64 a, u64 b) {
    asm("fma.rn.f32x2 %0, %1, %2, %0;" : "+l"(d) : "l"(a), "l"(b));
}
__device__ __forceinline__ void fadd2(u64& d, u64 a) {
    asm("add.rn.f32x2 %0, %1, %0;" : "+l"(d) : "l"(a));
}

// ---------------------------------------------------------------------------
// Pass 1: conv + bias; per-window sign-adjusted max; per-(b,g) partial stats.
// Grid: (32 row-groups, 128 batches, 2 channel-halves), block = 256.
// Thread t: wx = t&31 (4-col window), cb = t>>5 -> channels z*32+cb*4..+3.
// Warp (fixed cb) owns exactly GroupNorm group g = z*8+cb.
// f32x2 packed over CHANNEL pairs: weight pairs come free from scalar smem
// via LDS.128; only x needs (x,x) dup (6 MOVs per cin,ky). cin loop unroll 1.
// ---------------------------------------------------------------------------
__global__ __launch_bounds__(256, 2) void conv_pass1(const float* __restrict__ x,
                                                     const float* __restrict__ w,
                                                     const float* __restrict__ bias,
                                                     const float* __restrict__ gnw,
                                                     const float* __restrict__ scale)
{
    const int pr = blockIdx.x;          // 0..31
    const int b  = blockIdx.y;
    const int z  = blockIdx.z;          // channel half
    const int t  = threadIdx.x;

    __shared__ float xs[CIN][6][132];   // 6 input rows, 128 cols + 4 zero pad
    __shared__ float wsm[72][32];       // [cin*9+ky*3+kx][cl]  scalar, no dup
    __shared__ float bsm[32];
    __shared__ float sgsm[32];          // +1 / -1 per channel

    // weights for this half: global layout [co][cin][ky][kx]
    for (int i = t; i < 72 * 32; i += 256) {
        int cl = i & 31, k = i >> 5;
        wsm[k][cl] = w[(z * 32 + cl) * 72 + k];
    }
    if (t < 32) {
        bsm[t]  = bias[z * 32 + t];
        sgsm[t] = (gnw[z * 32 + t] * scale[z * 32 + t] < 0.f) ? -1.f : 1.f;
    }

    const int h0 = pr * 4;
    for (int i = t; i < CIN * 6 * 32; i += 256) {
        int c4  = i & 31;
        int rr  = (i >> 5) % 6;
        int cin = i / (6 * 32);
        int h   = h0 + rr;
        float4 v = make_float4(0.f, 0.f, 0.f, 0.f);
        if (h < HIN)
            v = *(const float4*)&x[(((size_t)b * CIN + cin) * HIN + h) * WIN + c4 * 4];
        *(float4*)&xs[cin][rr][c4 * 4] = v;
    }
    if (t < CIN * 6) {
        int rr = t % 6, cin = t / 6;
        *(float4*)&xs[cin][rr][128] = make_float4(0.f, 0.f, 0.f, 0.f);
    }
    __syncthreads();

    const int wx   = t & 31;
    const int cb   = t >> 5;
    const int col0 = wx * 4;
    const int R    = (pr == 31) ? 2 : 4;

    // hoisted per-channel-pair constants
    u64 bp[2];                          // bias pairs (b0,b1), (b2,b3)
    bp[0] = *(const u64*)&bsm[cb * 4 + 0];
    bp[1] = *(const u64*)&bsm[cb * 4 + 2];
    float sg[4];
#pragma unroll
    for (int j = 0; j < 4; j++) sg[j] = sgsm[cb * 4 + j];

    float wext[4];
#pragma unroll
    for (int j = 0; j < 4; j++) wext[j] = -1e30f;
    u64 s2 = 0ULL, q2 = 0ULL;           // packed (even-ch, odd-ch) stats

#pragma unroll 1
    for (int r = 0; r < R; r++) {
        u64 acc[2][4];                  // [channel pair][column]
#pragma unroll
        for (int p = 0; p < 2; p++)
#pragma unroll
            for (int c = 0; c < 4; c++) acc[p][c] = 0ULL;

#pragma unroll 1
        for (int cin = 0; cin < CIN; cin++) {
#pragma unroll
            for (int ky = 0; ky < 3; ky++) {
                const float* xr = &xs[cin][r + ky][col0];
                float4 xa = *(const float4*)xr;
                float2 xb = *(const float2*)(xr + 4);
                u64 xd[6];
                xd[0] = pk2(xa.x, xa.x); xd[1] = pk2(xa.y, xa.y);
                xd[2] = pk2(xa.z, xa.z); xd[3] = pk2(xa.w, xa.w);
                xd[4] = pk2(xb.x, xb.x); xd[5] = pk2(xb.y, xb.y);
                // 3 taps, each LDS.128 -> two channel-pair u64s
                ulonglong2 W0 = *(const ulonglong2*)&wsm[cin * 9 + ky * 3 + 0][cb * 4];
                ulonglong2 W1 = *(const ulonglong2*)&wsm[cin * 9 + ky * 3 + 1][cb * 4];
                ulonglong2 W2 = *(const ulonglong2*)&wsm[cin * 9 + ky * 3 + 2][cb * 4];
#pragma unroll
                for (int c = 0; c < 4; c++) {
                    ffma2(acc[0][c], W0.x, xd[c + 0]);
                    ffma2(acc[0][c], W1.x, xd[c + 1]);
                    ffma2(acc[0][c], W2.x, xd[c + 2]);
                    ffma2(acc[1][c], W0.y, xd[c + 0]);
                    ffma2(acc[1][c], W1.y, xd[c + 1]);
                    ffma2(acc[1][c], W2.y, xd[c + 2]);
                }
            }
        }

        // epilogue: bias, stats, sign-adjusted window max
#pragma unroll
        for (int p = 0; p < 2; p++) {
#pragma unroll
            for (int c = 0; c < 4; c++) {
                u64 a = acc[p][c];
                fadd2(a, bp[p]);
                if (wx < 31 || c < 2) {     // real column (<126)
                    fadd2(s2, a);
                    ffma2(q2, a, a);
                }
                if (wx < 31) {              // real pooled window
                    float v0, v1;
                    upk2(v0, v1, a);
                    int j0 = 2 * p, j1 = 2 * p + 1;
                    wext[j0] = fmaxf(wext[j0], sg[j0] * v0);
                    wext[j1] = fmaxf(wext[j1], sg[j1] * v1);
                }
            }
        }
    }

    // pooled window sign-adjusted max
    if (pr < 31 && wx < 31) {
#pragma unroll
        for (int j = 0; j < 4; j++) {
            int co = z * 32 + cb * 4 + j;
            size_t o = (((size_t)b * COUT + co) * PHN + pr) * PWN + wx;
            g_sext[o] = wext[j];
        }
    }

    // warp-level stats reduction; warp cb exclusively owns group z*8+cb
    float sl, sh, ql, qh;
    upk2(sl, sh, s2); upk2(ql, qh, q2);
    float s = sl + sh, q = ql + qh;
#pragma unroll
    for (int o = 16; o > 0; o >>= 1) {
        s += __shfl_down_sync(0xffffffffu, s, o);
        q += __shfl_down_sync(0xffffffffu, q, o);
    }
    if (wx == 0)
        g_partial[(pr * NB + b) * NG + z * 8 + cb] = make_float2(s, q);
}

// ---------------------------------------------------------------------------
// Pass 2: fold 32 row-group partials into mean/rstd per (b, g).
// ---------------------------------------------------------------------------
__global__ void stats_pass2()
{
    int idx = blockIdx.x * 256 + threadIdx.x;   // b*16+g
    if (idx >= NB * NG) return;
    float s = 0.f, q = 0.f;
    for (int pr = 0; pr < 32; pr++) {
        float2 p = g_partial[pr * (NB * NG) + idx];
        s += p.x; q += p.y;
    }
    const float inv = 1.f / (float)(CPG * HO * WO);
    float mean = s * inv;
    float var  = q * inv - mean * mean;
    g_stats[idx] = make_float2(mean, rsqrtf(var + 1e-5f));
}

// ---------------------------------------------------------------------------
// Pass 3: v = |A| * ext + B, clamp.  (ext = max of sign(A)-adjusted conv)
// ---------------------------------------------------------------------------
__global__ void apply_pass3(const float* __restrict__ gnw,
                            const float* __restrict__ gnb,
                            const float* __restrict__ scale,
                            float* __restrict__ out, int n)
{
    int idx = blockIdx.x * 256 + threadIdx.x;
    if (idx >= n) return;
    int tmp = idx / PWN;
    tmp /= PHN;
    int c = tmp % COUT;
    int b = tmp / COUT;

    float2 st = g_stats[b * NG + (c >> 2)];
    float gw = gnw[c], sc = scale[c];
    float A  = st.y * gw * sc;
    float Bt = (gnb[c] - st.x * st.y * gw) * sc;

    float v = fmaf(fabsf(A), g_sext[idx], Bt);
    out[idx] = fminf(fmaxf(v, 0.f), 1.f);
}

// ---------------------------------------------------------------------------
extern "C" void kernel_launch(void* const* d_in, const int* in_sizes, int n_in,
                              void* d_out, int out_size)
{
    const float* x     = (const float*)d_in[0];
    const float* w     = (const float*)d_in[1];
    const float* bias  = (const float*)d_in[2];
    const float* gnw   = (const float*)d_in[3];
    const float* gnb   = (const float*)d_in[4];
    const float* scale = (const float*)d_in[5];
    float* out = (float*)d_out;

    dim3 g1(32, NB, 2);
    conv_pass1<<<g1, 256>>>(x, w, bias, gnw, scale);
    stats_pass2<<<(NB * NG + 255) / 256, 256>>>();
    int n = NB * COUT * PHN * PWN;
    apply_pass3<<<(n + 255) / 256, 256>>>(gnw, gnb, scale, out, n);
}

// round 8
// speedup vs baseline: 1.3280x; 1.0456x over previous
#include <cuda_runtime.h>

#define NB    128
#define CIN   8
#define HIN   128
#define WIN   128
#define COUT  64
#define HO    126
#define WO    126
#define PHN   31
#define PWN   31
#define NG    16
#define CPG   4

typedef unsigned long long u64;

__device__ float  g_sext[(size_t)NB * COUT * PHN * PWN];   // max of sign-adjusted conv over window
__device__ float2 g_partial[32 * NB * NG];
__device__ float2 g_stats[NB * NG];

// ---- packed f32x2 helpers (sm_100+) ----
__device__ __forceinline__ u64 pk2(float lo, float hi) {
    u64 r; asm("mov.b64 %0, {%1, %2};" : "=l"(r) : "f"(lo), "f"(hi)); return r;
}
__device__ __forceinline__ void upk2(float& lo, float& hi, u64 p) {
    asm("mov.b64 {%0, %1}, %2;" : "=f"(lo), "=f"(hi) : "l"(p));
}
__device__ __forceinline__ void ffma2(u64& d, u64 a, u64 b) {
    asm("fma.rn.f32x2 %0, %1, %2, %0;" : "+l"(d) : "l"(a), "l"(b));
}
__device__ __forceinline__ void fadd2(u64& d, u64 a) {
    asm("add.rn.f32x2 %0, %1, %0;" : "+l"(d) : "l"(a));
}

// ---------------------------------------------------------------------------
// Pass 1: conv + bias; per-window sign-adjusted max; per-(b,g) partial stats.
// Grid: (32 row-groups, 128 batches), block = 256 = 16 col-threads x 16 cbs.
// Thread: kx = t&15 -> 8 output cols (2 pooling windows); cb = t>>4 -> 4
// channels cb*4..cb*4+3 (= GroupNorm group cb, owned by one half-warp).
// f32x2 packed over channel pairs; 8 cols amortize x/weight wavefronts.
// ---------------------------------------------------------------------------
__global__ __launch_bounds__(256, 2) void conv_pass1(const float* __restrict__ x,
                                                     const float* __restrict__ w,
                                                     const float* __restrict__ bias,
                                                     const float* __restrict__ gnw,
                                                     const float* __restrict__ scale)
{
    const int pr = blockIdx.x;          // 0..31
    const int b  = blockIdx.y;
    const int t  = threadIdx.x;

    __shared__ float xs[CIN][6][132];   // 6 input rows, 128 cols + 4 zero pad
    __shared__ float wsm[72][64];       // [cin*9+ky*3+kx][co]  scalar
    __shared__ float bsm[64];
    __shared__ float sgsm[64];          // +1 / -1 per channel

    // weights: global layout [co][cin][ky][kx]
    for (int i = t; i < 72 * 64; i += 256) {
        int cl = i & 63, k = i >> 6;
        wsm[k][cl] = w[cl * 72 + k];
    }
    if (t < 64) {
        bsm[t]  = bias[t];
        sgsm[t] = (gnw[t] * scale[t] < 0.f) ? -1.f : 1.f;
    }

    const int h0 = pr * 4;
    for (int i = t; i < CIN * 6 * 32; i += 256) {
        int c4  = i & 31;
        int rr  = (i >> 5) % 6;
        int cin = i / (6 * 32);
        int h   = h0 + rr;
        float4 v = make_float4(0.f, 0.f, 0.f, 0.f);
        if (h < HIN)
            v = *(const float4*)&x[(((size_t)b * CIN + cin) * HIN + h) * WIN + c4 * 4];
        *(float4*)&xs[cin][rr][c4 * 4] = v;
    }
    if (t < CIN * 6) {
        int rr = t % 6, cin = t / 6;
        *(float4*)&xs[cin][rr][128] = make_float4(0.f, 0.f, 0.f, 0.f);
    }
    __syncthreads();

    const int kx   = t & 15;
    const int cb   = t >> 4;
    const int col0 = kx * 8;
    const int R    = (pr == 31) ? 2 : 4;

    // hoisted per-channel constants
    u64 bp[2];
    bp[0] = *(const u64*)&bsm[cb * 4 + 0];
    bp[1] = *(const u64*)&bsm[cb * 4 + 2];
    float sg[4];
#pragma unroll
    for (int j = 0; j < 4; j++) sg[j] = sgsm[cb * 4 + j];

    float wext[4][2];                   // [channel][window 0/1]
#pragma unroll
    for (int j = 0; j < 4; j++) { wext[j][0] = -1e30f; wext[j][1] = -1e30f; }
    u64 s2 = 0ULL, q2 = 0ULL;           // packed (even-ch, odd-ch) stats

#pragma unroll 1
    for (int r = 0; r < R; r++) {
        u64 acc[2][8];                  // [channel pair][column]
#pragma unroll
        for (int p = 0; p < 2; p++)
#pragma unroll
            for (int c = 0; c < 8; c++) acc[p][c] = 0ULL;

#pragma unroll 1
        for (int cin = 0; cin < CIN; cin++) {
#pragma unroll
            for (int ky = 0; ky < 3; ky++) {
                const float* xr = &xs[cin][r + ky][col0];
                float4 xa = *(const float4*)xr;
                float4 xb = *(const float4*)(xr + 4);
                float2 xc = *(const float2*)(xr + 8);
                u64 xd[10];
                xd[0] = pk2(xa.x, xa.x); xd[1] = pk2(xa.y, xa.y);
                xd[2] = pk2(xa.z, xa.z); xd[3] = pk2(xa.w, xa.w);
                xd[4] = pk2(xb.x, xb.x); xd[5] = pk2(xb.y, xb.y);
                xd[6] = pk2(xb.z, xb.z); xd[7] = pk2(xb.w, xb.w);
                xd[8] = pk2(xc.x, xc.x); xd[9] = pk2(xc.y, xc.y);
                ulonglong2 W0 = *(const ulonglong2*)&wsm[cin * 9 + ky * 3 + 0][cb * 4];
                ulonglong2 W1 = *(const ulonglong2*)&wsm[cin * 9 + ky * 3 + 1][cb * 4];
                ulonglong2 W2 = *(const ulonglong2*)&wsm[cin * 9 + ky * 3 + 2][cb * 4];
#pragma unroll
                for (int c = 0; c < 8; c++) {
                    ffma2(acc[0][c], W0.x, xd[c + 0]);
                    ffma2(acc[0][c], W1.x, xd[c + 1]);
                    ffma2(acc[0][c], W2.x, xd[c + 2]);
                    ffma2(acc[1][c], W0.y, xd[c + 0]);
                    ffma2(acc[1][c], W1.y, xd[c + 1]);
                    ffma2(acc[1][c], W2.y, xd[c + 2]);
                }
            }
        }

        // epilogue: bias, stats, sign-adjusted window max
#pragma unroll
        for (int p = 0; p < 2; p++) {
#pragma unroll
            for (int c = 0; c < 8; c++) {
                u64 a = acc[p][c];
                fadd2(a, bp[p]);
                if (kx < 15 || c < 6) {     // real column (<126)
                    fadd2(s2, a);
                    ffma2(q2, a, a);
                }
                float v0, v1;
                upk2(v0, v1, a);
                int wi = c >> 2;
                int j0 = 2 * p, j1 = 2 * p + 1;
                wext[j0][wi] = fmaxf(wext[j0][wi], sg[j0] * v0);
                wext[j1][wi] = fmaxf(wext[j1][wi], sg[j1] * v1);
            }
        }
    }

    // pooled window sign-adjusted max (windows 2kx, 2kx+1; valid < 31)
    if (pr < 31) {
#pragma unroll
        for (int wi = 0; wi < 2; wi++) {
            int win = 2 * kx + wi;
            if (win < 31) {
#pragma unroll
                for (int j = 0; j < 4; j++) {
                    int co = cb * 4 + j;
                    size_t o = (((size_t)b * COUT + co) * PHN + pr) * PWN + win;
                    g_sext[o] = wext[j][wi];
                }
            }
        }
    }

    // half-warp stats reduction; half-warp (fixed cb) owns group cb
    float sl, sh, ql, qh;
    upk2(sl, sh, s2); upk2(ql, qh, q2);
    float s = sl + sh, q = ql + qh;
#pragma unroll
    for (int o = 8; o > 0; o >>= 1) {
        s += __shfl_down_sync(0xffffffffu, s, o, 16);
        q += __shfl_down_sync(0xffffffffu, q, o, 16);
    }
    if (kx == 0)
        g_partial[(pr * NB + b) * NG + cb] = make_float2(s, q);
}

// ---------------------------------------------------------------------------
// Pass 2: fold 32 row-group partials into mean/rstd per (b, g).
// ---------------------------------------------------------------------------
__global__ void stats_pass2()
{
    int idx = blockIdx.x * 256 + threadIdx.x;   // b*16+g
    if (idx >= NB * NG) return;
    float s = 0.f, q = 0.f;
    for (int pr = 0; pr < 32; pr++) {
        float2 p = g_partial[pr * (NB * NG) + idx];
        s += p.x; q += p.y;
    }
    const float inv = 1.f / (float)(CPG * HO * WO);
    float mean = s * inv;
    float var  = q * inv - mean * mean;
    g_stats[idx] = make_float2(mean, rsqrtf(var + 1e-5f));
}

// ---------------------------------------------------------------------------
// Pass 3: v = |A| * ext + B, clamp.  (ext = max of sign(A)-adjusted conv)
// ---------------------------------------------------------------------------
__global__ void apply_pass3(const float* __restrict__ gnw,
                            const float* __restrict__ gnb,
                            const float* __restrict__ scale,
                            float* __restrict__ out, int n)
{
    int idx = blockIdx.x * 256 + threadIdx.x;
    if (idx >= n) return;
    int tmp = idx / PWN;
    tmp /= PHN;
    int c = tmp % COUT;
    int b = tmp / COUT;

    float2 st = g_stats[b * NG + (c >> 2)];
    float gw = gnw[c], sc = scale[c];
    float A  = st.y * gw * sc;
    float Bt = (gnb[c] - st.x * st.y * gw) * sc;

    float v = fmaf(fabsf(A), g_sext[idx], Bt);
    out[idx] = fminf(fmaxf(v, 0.f), 1.f);
}

// ---------------------------------------------------------------------------
extern "C" void kernel_launch(void* const* d_in, const int* in_sizes, int n_in,
                              void* d_out, int out_size)
{
    const float* x     = (const float*)d_in[0];
    const float* w     = (const float*)d_in[1];
    const float* bias  = (const float*)d_in[2];
    const float* gnw   = (const float*)d_in[3];
    const float* gnb   = (const float*)d_in[4];
    const float* scale = (const float*)d_in[5];
    float* out = (float*)d_out;

    dim3 g1(32, NB);
    conv_pass1<<<g1, 256>>>(x, w, bias, gnw, scale);
    stats_pass2<<<(NB * NG + 255) / 256, 256>>>();
    int n = NB * COUT * PHN * PWN;
    apply_pass3<<<(n + 255) / 256, 256>>>(gnw, gnb, scale, out, n);
}

// round 9
// speedup vs baseline: 1.4134x; 1.0643x over previous
#include <cuda_runtime.h>

#define NB    128
#define CIN   8
#define HIN   128
#define WIN   128
#define COUT  64
#define HO    126
#define WO    126
#define PHN   31
#define PWN   31
#define NG    16
#define CPG   4

typedef unsigned long long u64;

__device__ float  g_sext[(size_t)NB * COUT * PHN * PWN];   // max of sign-adjusted conv over window
__device__ float2 g_partial[32 * NB * NG];
__device__ float2 g_stats[NB * NG];

// ---- packed f32x2 helpers (sm_100+) ----
__device__ __forceinline__ u64 pk2(float lo, float hi) {
    u64 r; asm("mov.b64 %0, {%1, %2};" : "=l"(r) : "f"(lo), "f"(hi)); return r;
}
__device__ __forceinline__ void upk2(float& lo, float& hi, u64 p) {
    asm("mov.b64 {%0, %1}, %2;" : "=f"(lo), "=f"(hi) : "l"(p));
}
__device__ __forceinline__ void ffma2(u64& d, u64 a, u64 b) {
    asm("fma.rn.f32x2 %0, %1, %2, %0;" : "+l"(d) : "l"(a), "l"(b));
}
__device__ __forceinline__ void fadd2(u64& d, u64 a) {
    asm("add.rn.f32x2 %0, %1, %0;" : "+l"(d) : "l"(a));
}

// ---------------------------------------------------------------------------
// Pass 1: conv + bias; per-window sign-adjusted max; per-(b,g) partial stats.
// Grid: (32 row-groups, 128 batches, 2 channel-halves), block = 256.
// Thread t: wx = t&31 (4-col window), cb = t>>5 -> channels z*32+cb*4..+3.
// Warp (fixed cb) owns exactly GroupNorm group g = z*8+cb.
// f32x2 packed over CHANNEL pairs (weights free via LDS.128 from scalar smem).
// launch_bounds(256,3): 85-reg target -> 3 CTAs/SM (24 warps) for latency hiding.
// ---------------------------------------------------------------------------
__global__ __launch_bounds__(256, 3) void conv_pass1(const float* __restrict__ x,
                                                     const float* __restrict__ w,
                                                     const float* __restrict__ bias,
                                                     const float* __restrict__ gnw,
                                                     const float* __restrict__ scale)
{
    const int pr = blockIdx.x;          // 0..31
    const int b  = blockIdx.y;
    const int z  = blockIdx.z;          // channel half
    const int t  = threadIdx.x;

    __shared__ float xs[CIN][6][132];   // 6 input rows, 128 cols + 4 zero pad
    __shared__ float wsm[72][32];       // [cin*9+ky*3+kx][cl]  scalar, no dup
    __shared__ float bsm[32];
    __shared__ float sgsm[32];          // +1 / -1 per channel

    // weights for this half: global layout [co][cin][ky][kx]
    for (int i = t; i < 72 * 32; i += 256) {
        int cl = i & 31, k = i >> 5;
        wsm[k][cl] = w[(z * 32 + cl) * 72 + k];
    }
    if (t < 32) {
        bsm[t]  = bias[z * 32 + t];
        sgsm[t] = (gnw[z * 32 + t] * scale[z * 32 + t] < 0.f) ? -1.f : 1.f;
    }

    const int h0 = pr * 4;
    for (int i = t; i < CIN * 6 * 32; i += 256) {
        int c4  = i & 31;
        int rr  = (i >> 5) % 6;
        int cin = i / (6 * 32);
        int h   = h0 + rr;
        float4 v = make_float4(0.f, 0.f, 0.f, 0.f);
        if (h < HIN)
            v = *(const float4*)&x[(((size_t)b * CIN + cin) * HIN + h) * WIN + c4 * 4];
        *(float4*)&xs[cin][rr][c4 * 4] = v;
    }
    if (t < CIN * 6) {
        int rr = t % 6, cin = t / 6;
        *(float4*)&xs[cin][rr][128] = make_float4(0.f, 0.f, 0.f, 0.f);
    }
    __syncthreads();

    const int wx   = t & 31;
    const int cb   = t >> 5;
    const int col0 = wx * 4;
    const int R    = (pr == 31) ? 2 : 4;

    // hoisted per-channel-pair constants
    u64 bp[2];                          // bias pairs (b0,b1), (b2,b3)
    bp[0] = *(const u64*)&bsm[cb * 4 + 0];
    bp[1] = *(const u64*)&bsm[cb * 4 + 2];
    float sg[4];
#pragma unroll
    for (int j = 0; j < 4; j++) sg[j] = sgsm[cb * 4 + j];

    float wext[4];
#pragma unroll
    for (int j = 0; j < 4; j++) wext[j] = -1e30f;
    u64 s2 = 0ULL, q2 = 0ULL;           // packed (even-ch, odd-ch) stats

#pragma unroll 1
    for (int r = 0; r < R; r++) {
        u64 acc[2][4];                  // [channel pair][column]
#pragma unroll
        for (int p = 0; p < 2; p++)
#pragma unroll
            for (int c = 0; c < 4; c++) acc[p][c] = 0ULL;

#pragma unroll 1
        for (int cin = 0; cin < CIN; cin++) {
#pragma unroll
            for (int ky = 0; ky < 3; ky++) {
                const float* xr = &xs[cin][r + ky][col0];
                float4 xa = *(const float4*)xr;
                float2 xb = *(const float2*)(xr + 4);
                u64 xd[6];
                xd[0] = pk2(xa.x, xa.x); xd[1] = pk2(xa.y, xa.y);
                xd[2] = pk2(xa.z, xa.z); xd[3] = pk2(xa.w, xa.w);
                xd[4] = pk2(xb.x, xb.x); xd[5] = pk2(xb.y, xb.y);
                // 3 taps, each LDS.128 -> two channel-pair u64s
                ulonglong2 W0 = *(const ulonglong2*)&wsm[cin * 9 + ky * 3 + 0][cb * 4];
                ulonglong2 W1 = *(const ulonglong2*)&wsm[cin * 9 + ky * 3 + 1][cb * 4];
                ulonglong2 W2 = *(const ulonglong2*)&wsm[cin * 9 + ky * 3 + 2][cb * 4];
#pragma unroll
                for (int c = 0; c < 4; c++) {
                    ffma2(acc[0][c], W0.x, xd[c + 0]);
                    ffma2(acc[0][c], W1.x, xd[c + 1]);
                    ffma2(acc[0][c], W2.x, xd[c + 2]);
                    ffma2(acc[1][c], W0.y, xd[c + 0]);
                    ffma2(acc[1][c], W1.y, xd[c + 1]);
                    ffma2(acc[1][c], W2.y, xd[c + 2]);
                }
            }
        }

        // epilogue: bias, stats, sign-adjusted window max
#pragma unroll
        for (int p = 0; p < 2; p++) {
#pragma unroll
            for (int c = 0; c < 4; c++) {
                u64 a = acc[p][c];
                fadd2(a, bp[p]);
                if (wx < 31 || c < 2) {     // real column (<126)
                    fadd2(s2, a);
                    ffma2(q2, a, a);
                }
                if (wx < 31) {              // real pooled window
                    float v0, v1;
                    upk2(v0, v1, a);
                    int j0 = 2 * p, j1 = 2 * p + 1;
                    wext[j0] = fmaxf(wext[j0], sg[j0] * v0);
                    wext[j1] = fmaxf(wext[j1], sg[j1] * v1);
                }
            }
        }
    }

    // pooled window sign-adjusted max
    if (pr < 31 && wx < 31) {
#pragma unroll
        for (int j = 0; j < 4; j++) {
            int co = z * 32 + cb * 4 + j;
            size_t o = (((size_t)b * COUT + co) * PHN + pr) * PWN + wx;
            g_sext[o] = wext[j];
        }
    }

    // warp-level stats reduction; warp cb exclusively owns group z*8+cb
    float sl, sh, ql, qh;
    upk2(sl, sh, s2); upk2(ql, qh, q2);
    float s = sl + sh, q = ql + qh;
#pragma unroll
    for (int o = 16; o > 0; o >>= 1) {
        s += __shfl_down_sync(0xffffffffu, s, o);
        q += __shfl_down_sync(0xffffffffu, q, o);
    }
    if (wx == 0)
        g_partial[(pr * NB + b) * NG + z * 8 + cb] = make_float2(s, q);
}

// ---------------------------------------------------------------------------
// Pass 2: fold 32 row-group partials into mean/rstd per (b, g).
// ---------------------------------------------------------------------------
__global__ void stats_pass2()
{
    int idx = blockIdx.x * 256 + threadIdx.x;   // b*16+g
    if (idx >= NB * NG) return;
    float s = 0.f, q = 0.f;
    for (int pr = 0; pr < 32; pr++) {
        float2 p = g_partial[pr * (NB * NG) + idx];
        s += p.x; q += p.y;
    }
    const float inv = 1.f / (float)(CPG * HO * WO);
    float mean = s * inv;
    float var  = q * inv - mean * mean;
    g_stats[idx] = make_float2(mean, rsqrtf(var + 1e-5f));
}

// ---------------------------------------------------------------------------
// Pass 3: v = |A| * ext + B, clamp.  (ext = max of sign(A)-adjusted conv)
// ---------------------------------------------------------------------------
__global__ void apply_pass3(const float* __restrict__ gnw,
                            const float* __restrict__ gnb,
                            const float* __restrict__ scale,
                            float* __restrict__ out, int n)
{
    int idx = blockIdx.x * 256 + threadIdx.x;
    if (idx >= n) return;
    int tmp = idx / PWN;
    tmp /= PHN;
    int c = tmp % COUT;
    int b = tmp / COUT;

    float2 st = g_stats[b * NG + (c >> 2)];
    float gw = gnw[c], sc = scale[c];
    float A  = st.y * gw * sc;
    float Bt = (gnb[c] - st.x * st.y * gw) * sc;

    float v = fmaf(fabsf(A), g_sext[idx], Bt);
    out[idx] = fminf(fmaxf(v, 0.f), 1.f);
}

// ---------------------------------------------------------------------------
extern "C" void kernel_launch(void* const* d_in, const int* in_sizes, int n_in,
                              void* d_out, int out_size)
{
    const float* x     = (const float*)d_in[0];
    const float* w     = (const float*)d_in[1];
    const float* bias  = (const float*)d_in[2];
    const float* gnw   = (const float*)d_in[3];
    const float* gnb   = (const float*)d_in[4];
    const float* scale = (const float*)d_in[5];
    float* out = (float*)d_out;

    dim3 g1(32, NB, 2);
    conv_pass1<<<g1, 256>>>(x, w, bias, gnw, scale);
    stats_pass2<<<(NB * NG + 255) / 256, 256>>>();
    int n = NB * COUT * PHN * PWN;
    apply_pass3<<<(n + 255) / 256, 256>>>(gnw, gnb, scale, out, n);
}